// round 5
// baseline (speedup 1.0000x reference)
#include <cuda_runtime.h>

#define N_HID     128
#define N_ETYPES  10
#define N_EDGES   100000
#define TOTAL_EDGES (N_ETYPES * N_EDGES)
#define EPW       4
#define NGROUPS   (TOTAL_EDGES / EPW)   // 250000

// Persistent warps, double-buffered pipeline: while a warp reduces group i,
// the 8 gathers of group i+stride are already in flight. Keeps the L1tex
// pipe (the saturating resource) continuously fed.
__device__ __forceinline__ void issue_group(
    const float* __restrict__ h,
    const int* __restrict__ src, const int* __restrict__ dst,
    int e0, int lane,
    float4& a0, float4& a1, float4& a2, float4& a3,
    float4& b0, float4& b1, float4& b2, float4& b3)
{
    const int4 s4 = __ldg((const int4*)(src + e0));
    const int4 d4 = __ldg((const int4*)(dst + e0));
    a0 = __ldg((const float4*)(h + (size_t)s4.x * N_HID) + lane);
    a1 = __ldg((const float4*)(h + (size_t)s4.y * N_HID) + lane);
    a2 = __ldg((const float4*)(h + (size_t)s4.z * N_HID) + lane);
    a3 = __ldg((const float4*)(h + (size_t)s4.w * N_HID) + lane);
    b0 = __ldg((const float4*)(h + (size_t)d4.x * N_HID) + lane);
    b1 = __ldg((const float4*)(h + (size_t)d4.y * N_HID) + lane);
    b2 = __ldg((const float4*)(h + (size_t)d4.z * N_HID) + lane);
    b3 = __ldg((const float4*)(h + (size_t)d4.w * N_HID) + lane);
}

__device__ __forceinline__ void consume_group(
    const float* __restrict__ W, const int* __restrict__ rel,
    float* __restrict__ out, int e0, int lane,
    const float4& a0, const float4& a1, const float4& a2, const float4& a3,
    const float4& b0, const float4& b1, const float4& b2, const float4& b3)
{
    const int t = e0 / N_EDGES;       // e0 % 4 == 0, never straddles etypes
    const int r = __ldg(&rel[t]);
    const float4 w = __ldg((const float4*)(W + r * N_HID) + lane);

    float acc0 = a0.x * w.x * b0.x;
    acc0 = fmaf(a0.y * w.y, b0.y, acc0);
    acc0 = fmaf(a0.z * w.z, b0.z, acc0);
    acc0 = fmaf(a0.w * w.w, b0.w, acc0);
    float acc1 = a1.x * w.x * b1.x;
    acc1 = fmaf(a1.y * w.y, b1.y, acc1);
    acc1 = fmaf(a1.z * w.z, b1.z, acc1);
    acc1 = fmaf(a1.w * w.w, b1.w, acc1);
    float acc2 = a2.x * w.x * b2.x;
    acc2 = fmaf(a2.y * w.y, b2.y, acc2);
    acc2 = fmaf(a2.z * w.z, b2.z, acc2);
    acc2 = fmaf(a2.w * w.w, b2.w, acc2);
    float acc3 = a3.x * w.x * b3.x;
    acc3 = fmaf(a3.y * w.y, b3.y, acc3);
    acc3 = fmaf(a3.z * w.z, b3.z, acc3);
    acc3 = fmaf(a3.w * w.w, b3.w, acc3);

    // butterfly 16,8 -> value depends only on lane&7
    #pragma unroll
    for (int off = 16; off >= 8; off >>= 1) {
        acc0 += __shfl_xor_sync(0xffffffffu, acc0, off);
        acc1 += __shfl_xor_sync(0xffffffffu, acc1, off);
        acc2 += __shfl_xor_sync(0xffffffffu, acc2, off);
        acc3 += __shfl_xor_sync(0xffffffffu, acc3, off);
    }
    // each octet adopts one acc, finish within octet
    const int g = lane >> 3;
    float sel = (g == 0) ? acc0 : (g == 1) ? acc1 : (g == 2) ? acc2 : acc3;
    #pragma unroll
    for (int off = 4; off > 0; off >>= 1)
        sel += __shfl_xor_sync(0xffffffffu, sel, off);

    if ((lane & 7) == 0)
        out[e0 + g] = 1.0f / (1.0f + __expf(-sel));
}

__global__ void __launch_bounds__(256) distmult_kernel(
    const float* __restrict__ h,
    const float* __restrict__ W,
    const int* __restrict__ src,
    const int* __restrict__ dst,
    const int* __restrict__ rel,
    float* __restrict__ out)
{
    const int warp   = (blockIdx.x * blockDim.x + threadIdx.x) >> 5;
    const int nwarps = (gridDim.x * blockDim.x) >> 5;
    const int lane   = threadIdx.x & 31;

    int g = warp;
    if (g >= NGROUPS) return;

    float4 xa0, xa1, xa2, xa3, xb0, xb1, xb2, xb3;   // stage X
    float4 ya0, ya1, ya2, ya3, yb0, yb1, yb2, yb3;   // stage Y

    issue_group(h, src, dst, g * EPW, lane, xa0, xa1, xa2, xa3, xb0, xb1, xb2, xb3);

    while (true) {
        // --- half 1: prefetch into Y, consume X ---
        const int gn = g + nwarps;
        const bool vn = gn < NGROUPS;
        if (vn)
            issue_group(h, src, dst, gn * EPW, lane, ya0, ya1, ya2, ya3, yb0, yb1, yb2, yb3);
        consume_group(W, rel, out, g * EPW, lane, xa0, xa1, xa2, xa3, xb0, xb1, xb2, xb3);
        if (!vn) break;

        // --- half 2: prefetch into X, consume Y ---
        const int gnn = gn + nwarps;
        const bool vnn = gnn < NGROUPS;
        if (vnn)
            issue_group(h, src, dst, gnn * EPW, lane, xa0, xa1, xa2, xa3, xb0, xb1, xb2, xb3);
        consume_group(W, rel, out, gn * EPW, lane, ya0, ya1, ya2, ya3, yb0, yb1, yb2, yb3);
        if (!vnn) break;

        g = gnn;
    }
}

extern "C" void kernel_launch(void* const* d_in, const int* in_sizes, int n_in,
                              void* d_out, int out_size)
{
    const float* h   = (const float*)d_in[0];   // [N_NODES, 128]
    const float* W   = (const float*)d_in[1];   // [10, 128]
    const int*   src = (const int*)d_in[2];     // [10, 100000] int32
    const int*   dst = (const int*)d_in[3];     // [10, 100000] int32
    const int*   rel = (const int*)d_in[4];     // [10] int32
    float* out = (float*)d_out;                 // [10, 100000]

    const int threads = 256;
    const int blocks  = 592;   // 4 per SM nominal; persistent grid-stride
    distmult_kernel<<<blocks, threads>>>(h, W, src, dst, rel, out);
}

// round 7
// speedup vs baseline: 1.5767x; 1.5767x over previous
#include <cuda_runtime.h>

#define N_HID     128
#define N_ETYPES  10
#define N_EDGES   100000
#define TOTAL_EDGES (N_ETYPES * N_EDGES)
#define EPW       8   // edges per warp

// One warp per 8 consecutive edges. Each lane owns 4 dims (float4) of each edge.
// 16 independent 512B gathers. Optimal multi-value reduction: mux after every
// butterfly stage -> 16 SHFL + 7 SEL per 8 edges (vs 22 SHFL in R4).
__global__ void __launch_bounds__(128) distmult_kernel(
    const float* __restrict__ h,
    const float* __restrict__ W,
    const int* __restrict__ src,
    const int* __restrict__ dst,
    const int* __restrict__ rel,
    float* __restrict__ out)
{
    const int warp = (blockIdx.x * blockDim.x + threadIdx.x) >> 5;
    const int lane = threadIdx.x & 31;
    const int e0 = warp * EPW;
    if (e0 >= TOTAL_EDGES) return;

    const int t = e0 / N_EDGES;            // 100000 % 8 == 0: no etype straddle
    const int r = __ldg(&rel[t]);

    const int4 sA = __ldg((const int4*)(src + e0));
    const int4 sB = __ldg((const int4*)(src + e0 + 4));
    const int4 dA = __ldg((const int4*)(dst + e0));
    const int4 dB = __ldg((const int4*)(dst + e0 + 4));

    const float4 w = __ldg((const float4*)(W + r * N_HID) + lane);

    // 16 independent gathers — issue all before consuming any
    const float4 a0 = __ldg((const float4*)(h + (size_t)sA.x * N_HID) + lane);
    const float4 a1 = __ldg((const float4*)(h + (size_t)sA.y * N_HID) + lane);
    const float4 a2 = __ldg((const float4*)(h + (size_t)sA.z * N_HID) + lane);
    const float4 a3 = __ldg((const float4*)(h + (size_t)sA.w * N_HID) + lane);
    const float4 a4 = __ldg((const float4*)(h + (size_t)sB.x * N_HID) + lane);
    const float4 a5 = __ldg((const float4*)(h + (size_t)sB.y * N_HID) + lane);
    const float4 a6 = __ldg((const float4*)(h + (size_t)sB.z * N_HID) + lane);
    const float4 a7 = __ldg((const float4*)(h + (size_t)sB.w * N_HID) + lane);
    const float4 b0 = __ldg((const float4*)(h + (size_t)dA.x * N_HID) + lane);
    const float4 b1 = __ldg((const float4*)(h + (size_t)dA.y * N_HID) + lane);
    const float4 b2 = __ldg((const float4*)(h + (size_t)dA.z * N_HID) + lane);
    const float4 b3 = __ldg((const float4*)(h + (size_t)dA.w * N_HID) + lane);
    const float4 b4 = __ldg((const float4*)(h + (size_t)dB.x * N_HID) + lane);
    const float4 b5 = __ldg((const float4*)(h + (size_t)dB.y * N_HID) + lane);
    const float4 b6 = __ldg((const float4*)(h + (size_t)dB.z * N_HID) + lane);
    const float4 b7 = __ldg((const float4*)(h + (size_t)dB.w * N_HID) + lane);

#define DOT(acc, a, b)                    \
    float acc = a.x * w.x * b.x;          \
    acc = fmaf(a.y * w.y, b.y, acc);      \
    acc = fmaf(a.z * w.z, b.z, acc);      \
    acc = fmaf(a.w * w.w, b.w, acc);

    DOT(acc0, a0, b0) DOT(acc1, a1, b1) DOT(acc2, a2, b2) DOT(acc3, a3, b3)
    DOT(acc4, a4, b4) DOT(acc5, a5, b5) DOT(acc6, a6, b6) DOT(acc7, a7, b7)
#undef DOT

    // Stage 1: offset 16 on all 8 accs (8 SHFL), then mux on bit4 (edge bit +4)
    acc0 += __shfl_xor_sync(0xffffffffu, acc0, 16);
    acc1 += __shfl_xor_sync(0xffffffffu, acc1, 16);
    acc2 += __shfl_xor_sync(0xffffffffu, acc2, 16);
    acc3 += __shfl_xor_sync(0xffffffffu, acc3, 16);
    acc4 += __shfl_xor_sync(0xffffffffu, acc4, 16);
    acc5 += __shfl_xor_sync(0xffffffffu, acc5, 16);
    acc6 += __shfl_xor_sync(0xffffffffu, acc6, 16);
    acc7 += __shfl_xor_sync(0xffffffffu, acc7, 16);
    const bool hi4 = lane & 16;
    float v0 = hi4 ? acc4 : acc0;
    float v1 = hi4 ? acc5 : acc1;
    float v2 = hi4 ? acc6 : acc2;
    float v3 = hi4 ? acc7 : acc3;

    // Stage 2: offset 8 on 4 values (4 SHFL), mux on bit3 (edge bit +2)
    v0 += __shfl_xor_sync(0xffffffffu, v0, 8);
    v1 += __shfl_xor_sync(0xffffffffu, v1, 8);
    v2 += __shfl_xor_sync(0xffffffffu, v2, 8);
    v3 += __shfl_xor_sync(0xffffffffu, v3, 8);
    const bool hi3 = lane & 8;
    float u0 = hi3 ? v2 : v0;
    float u1 = hi3 ? v3 : v1;

    // Stage 3: offset 4 on 2 values (2 SHFL), mux on bit2 (edge bit +1)
    u0 += __shfl_xor_sync(0xffffffffu, u0, 4);
    u1 += __shfl_xor_sync(0xffffffffu, u1, 4);
    float s = (lane & 4) ? u1 : u0;

    // Stage 4+5: finish within quad (2 SHFL)
    s += __shfl_xor_sync(0xffffffffu, s, 2);
    s += __shfl_xor_sync(0xffffffffu, s, 1);

    // quad-leader lane 4m holds edge e = lane>>2; 8 consecutive stores
    const float sig = 1.0f / (1.0f + __expf(-s));
    if ((lane & 3) == 0)
        out[e0 + (lane >> 2)] = sig;
}

extern "C" void kernel_launch(void* const* d_in, const int* in_sizes, int n_in,
                              void* d_out, int out_size)
{
    const float* h   = (const float*)d_in[0];   // [N_NODES, 128]
    const float* W   = (const float*)d_in[1];   // [10, 128]
    const int*   src = (const int*)d_in[2];     // [10, 100000] int32
    const int*   dst = (const int*)d_in[3];     // [10, 100000] int32
    const int*   rel = (const int*)d_in[4];     // [10] int32
    float* out = (float*)d_out;                 // [10, 100000]

    const int threads = 128;                    // 4 warps/block, 32 edges/block
    const int warps_needed = TOTAL_EDGES / EPW; // 125000
    const int blocks = (warps_needed * 32 + threads - 1) / threads;
    distmult_kernel<<<blocks, threads>>>(h, W, src, dst, rel, out);
}

// round 8
// speedup vs baseline: 1.7395x; 1.1033x over previous
#include <cuda_runtime.h>

#define N_HID     128
#define N_ETYPES  10
#define N_EDGES   100000
#define TOTAL_EDGES (N_ETYPES * N_EDGES)
#define EPW       16   // edges per warp

// One warp per 16 consecutive edges. Each lane owns 4 dims (float4) per edge.
// launch_bounds(128,6) caps regs ~85 so ~14-16 gathers are truly in flight
// (R4/R7 at 42 regs had only ~6). Two 16-gather halves; mux-per-stage
// reduction (31 SHFL / 16 edges); even lanes store 64B coalesced.
__global__ void __launch_bounds__(128, 6) distmult_kernel(
    const float* __restrict__ h,
    const float* __restrict__ W,
    const int* __restrict__ src,
    const int* __restrict__ dst,
    const int* __restrict__ rel,
    float* __restrict__ out)
{
    const int warp = (blockIdx.x * blockDim.x + threadIdx.x) >> 5;
    const int lane = threadIdx.x & 31;
    const int e0 = warp * EPW;
    if (e0 >= TOTAL_EDGES) return;

    const int t = e0 / N_EDGES;            // 100000 % 16 == 0: no straddle
    const int r = __ldg(&rel[t]);
    const float4 w = __ldg((const float4*)(W + r * N_HID) + lane);

    const int4 s0 = __ldg((const int4*)(src + e0));
    const int4 s1 = __ldg((const int4*)(src + e0 + 4));
    const int4 s2 = __ldg((const int4*)(src + e0 + 8));
    const int4 s3 = __ldg((const int4*)(src + e0 + 12));
    const int4 d0 = __ldg((const int4*)(dst + e0));
    const int4 d1 = __ldg((const int4*)(dst + e0 + 4));
    const int4 d2 = __ldg((const int4*)(dst + e0 + 8));
    const int4 d3 = __ldg((const int4*)(dst + e0 + 12));

    float acc[16];

#define GATHER(va, vb, sidx, didx)                                          \
    {                                                                       \
        va = __ldg((const float4*)(h + (size_t)(sidx) * N_HID) + lane);     \
        vb = __ldg((const float4*)(h + (size_t)(didx) * N_HID) + lane);     \
    }
#define DOT(k, a, b)                                                        \
    {                                                                       \
        float x = a.x * w.x * b.x;                                          \
        x = fmaf(a.y * w.y, b.y, x);                                        \
        x = fmaf(a.z * w.z, b.z, x);                                        \
        acc[k] = fmaf(a.w * w.w, b.w, x);                                   \
    }

    // ---- half A: edges 0..7, 16 gathers batched ----
    {
        float4 a0, a1, a2, a3, a4, a5, a6, a7;
        float4 b0, b1, b2, b3, b4, b5, b6, b7;
        GATHER(a0, b0, s0.x, d0.x) GATHER(a1, b1, s0.y, d0.y)
        GATHER(a2, b2, s0.z, d0.z) GATHER(a3, b3, s0.w, d0.w)
        GATHER(a4, b4, s1.x, d1.x) GATHER(a5, b5, s1.y, d1.y)
        GATHER(a6, b6, s1.z, d1.z) GATHER(a7, b7, s1.w, d1.w)
        DOT(0, a0, b0) DOT(1, a1, b1) DOT(2, a2, b2) DOT(3, a3, b3)
        DOT(4, a4, b4) DOT(5, a5, b5) DOT(6, a6, b6) DOT(7, a7, b7)
    }
    // ---- half B: edges 8..15 ----
    {
        float4 a0, a1, a2, a3, a4, a5, a6, a7;
        float4 b0, b1, b2, b3, b4, b5, b6, b7;
        GATHER(a0, b0, s2.x, d2.x) GATHER(a1, b1, s2.y, d2.y)
        GATHER(a2, b2, s2.z, d2.z) GATHER(a3, b3, s2.w, d2.w)
        GATHER(a4, b4, s3.x, d3.x) GATHER(a5, b5, s3.y, d3.y)
        GATHER(a6, b6, s3.z, d3.z) GATHER(a7, b7, s3.w, d3.w)
        DOT(8,  a0, b0) DOT(9,  a1, b1) DOT(10, a2, b2) DOT(11, a3, b3)
        DOT(12, a4, b4) DOT(13, a5, b5) DOT(14, a6, b6) DOT(15, a7, b7)
    }
#undef GATHER
#undef DOT

    // ---- reduction: mux after every butterfly stage ----
    // Stage 1: offset 16 (16 SHFL), mux on lane bit4 -> 8 values (edge +8)
    #pragma unroll
    for (int k = 0; k < 16; k++)
        acc[k] += __shfl_xor_sync(0xffffffffu, acc[k], 16);
    const bool h4 = lane & 16;
    float v[8];
    #pragma unroll
    for (int k = 0; k < 8; k++)
        v[k] = h4 ? acc[k + 8] : acc[k];

    // Stage 2: offset 8 (8 SHFL), mux on bit3 -> 4 values (edge +4)
    #pragma unroll
    for (int k = 0; k < 8; k++)
        v[k] += __shfl_xor_sync(0xffffffffu, v[k], 8);
    const bool h3 = lane & 8;
    float u[4];
    #pragma unroll
    for (int k = 0; k < 4; k++)
        u[k] = h3 ? v[k + 4] : v[k];

    // Stage 3: offset 4 (4 SHFL), mux on bit2 -> 2 values (edge +2)
    #pragma unroll
    for (int k = 0; k < 4; k++)
        u[k] += __shfl_xor_sync(0xffffffffu, u[k], 4);
    const bool h2 = lane & 4;
    float p0 = h2 ? u[2] : u[0];
    float p1 = h2 ? u[3] : u[1];

    // Stage 4: offset 2 (2 SHFL), mux on bit1 -> 1 value (edge +1)
    p0 += __shfl_xor_sync(0xffffffffu, p0, 2);
    p1 += __shfl_xor_sync(0xffffffffu, p1, 2);
    float s = (lane & 2) ? p1 : p0;

    // Stage 5: offset 1 — lane pair {2e, 2e+1} now holds edge e = lane>>1
    s += __shfl_xor_sync(0xffffffffu, s, 1);

    const float sig = 1.0f / (1.0f + __expf(-s));
    if ((lane & 1) == 0)
        out[e0 + (lane >> 1)] = sig;   // 16 consecutive floats, one wavefront
}

extern "C" void kernel_launch(void* const* d_in, const int* in_sizes, int n_in,
                              void* d_out, int out_size)
{
    const float* h   = (const float*)d_in[0];   // [N_NODES, 128]
    const float* W   = (const float*)d_in[1];   // [10, 128]
    const int*   src = (const int*)d_in[2];     // [10, 100000] int32
    const int*   dst = (const int*)d_in[3];     // [10, 100000] int32
    const int*   rel = (const int*)d_in[4];     // [10] int32
    float* out = (float*)d_out;                 // [10, 100000]

    const int threads = 128;                     // 4 warps/block, 64 edges/block
    const int warps_needed = TOTAL_EDGES / EPW;  // 62500
    const int blocks = (warps_needed * 32 + threads - 1) / threads;  // 15625
    distmult_kernel<<<blocks, threads>>>(h, W, src, dst, rel, out);
}

// round 9
// speedup vs baseline: 1.7962x; 1.0326x over previous
#include <cuda_runtime.h>

#define N_HID     128
#define N_ETYPES  10
#define N_EDGES   100000
#define TOTAL_EDGES (N_ETYPES * N_EDGES)
#define EPW       16   // edges per warp

// One warp per 16 consecutive edges; 4 quarters of 8 batched gathers each.
// launch_bounds(128,8) caps regs at 64 -> 8 blocks/SM (32 warps, 50% occ).
// 32 warps x ~32 queued wavefronts each keeps the L1tex queue (~248) full
// continuously, unlike R8's 21 warps with bursty issue.
__global__ void __launch_bounds__(128, 8) distmult_kernel(
    const float* __restrict__ h,
    const float* __restrict__ W,
    const int* __restrict__ src,
    const int* __restrict__ dst,
    const int* __restrict__ rel,
    float* __restrict__ out)
{
    const int warp = (blockIdx.x * blockDim.x + threadIdx.x) >> 5;
    const int lane = threadIdx.x & 31;
    const int e0 = warp * EPW;
    if (e0 >= TOTAL_EDGES) return;

    const int t = e0 / N_EDGES;            // 100000 % 16 == 0: no straddle
    const int r = __ldg(&rel[t]);
    const float4 w = __ldg((const float4*)(W + r * N_HID) + lane);

    float acc[16];

#define QUARTER(base, sv, dv)                                                \
    {                                                                        \
        const int4 s4 = sv;                                                  \
        const int4 d4 = dv;                                                  \
        float4 a0 = __ldg((const float4*)(h + (size_t)s4.x * N_HID) + lane); \
        float4 a1 = __ldg((const float4*)(h + (size_t)s4.y * N_HID) + lane); \
        float4 a2 = __ldg((const float4*)(h + (size_t)s4.z * N_HID) + lane); \
        float4 a3 = __ldg((const float4*)(h + (size_t)s4.w * N_HID) + lane); \
        float4 b0 = __ldg((const float4*)(h + (size_t)d4.x * N_HID) + lane); \
        float4 b1 = __ldg((const float4*)(h + (size_t)d4.y * N_HID) + lane); \
        float4 b2 = __ldg((const float4*)(h + (size_t)d4.z * N_HID) + lane); \
        float4 b3 = __ldg((const float4*)(h + (size_t)d4.w * N_HID) + lane); \
        float x;                                                             \
        x = a0.x * w.x * b0.x;                                               \
        x = fmaf(a0.y * w.y, b0.y, x);                                       \
        x = fmaf(a0.z * w.z, b0.z, x);                                       \
        acc[base + 0] = fmaf(a0.w * w.w, b0.w, x);                           \
        x = a1.x * w.x * b1.x;                                               \
        x = fmaf(a1.y * w.y, b1.y, x);                                       \
        x = fmaf(a1.z * w.z, b1.z, x);                                       \
        acc[base + 1] = fmaf(a1.w * w.w, b1.w, x);                           \
        x = a2.x * w.x * b2.x;                                               \
        x = fmaf(a2.y * w.y, b2.y, x);                                       \
        x = fmaf(a2.z * w.z, b2.z, x);                                       \
        acc[base + 2] = fmaf(a2.w * w.w, b2.w, x);                           \
        x = a3.x * w.x * b3.x;                                               \
        x = fmaf(a3.y * w.y, b3.y, x);                                       \
        x = fmaf(a3.z * w.z, b3.z, x);                                       \
        acc[base + 3] = fmaf(a3.w * w.w, b3.w, x);                           \
    }

    QUARTER(0,  __ldg((const int4*)(src + e0)),      __ldg((const int4*)(dst + e0)))
    QUARTER(4,  __ldg((const int4*)(src + e0 + 4)),  __ldg((const int4*)(dst + e0 + 4)))
    QUARTER(8,  __ldg((const int4*)(src + e0 + 8)),  __ldg((const int4*)(dst + e0 + 8)))
    QUARTER(12, __ldg((const int4*)(src + e0 + 12)), __ldg((const int4*)(dst + e0 + 12)))
#undef QUARTER

    // ---- reduction: mux after every butterfly stage (31 SHFL / 16 edges) ----
    #pragma unroll
    for (int k = 0; k < 16; k++)
        acc[k] += __shfl_xor_sync(0xffffffffu, acc[k], 16);
    const bool h4 = lane & 16;
    float v[8];
    #pragma unroll
    for (int k = 0; k < 8; k++)
        v[k] = h4 ? acc[k + 8] : acc[k];

    #pragma unroll
    for (int k = 0; k < 8; k++)
        v[k] += __shfl_xor_sync(0xffffffffu, v[k], 8);
    const bool h3 = lane & 8;
    float u[4];
    #pragma unroll
    for (int k = 0; k < 4; k++)
        u[k] = h3 ? v[k + 4] : v[k];

    #pragma unroll
    for (int k = 0; k < 4; k++)
        u[k] += __shfl_xor_sync(0xffffffffu, u[k], 4);
    const bool h2 = lane & 4;
    float p0 = h2 ? u[2] : u[0];
    float p1 = h2 ? u[3] : u[1];

    p0 += __shfl_xor_sync(0xffffffffu, p0, 2);
    p1 += __shfl_xor_sync(0xffffffffu, p1, 2);
    float s = (lane & 2) ? p1 : p0;

    s += __shfl_xor_sync(0xffffffffu, s, 1);

    const float sig = 1.0f / (1.0f + __expf(-s));
    if ((lane & 1) == 0)
        out[e0 + (lane >> 1)] = sig;   // 16 consecutive floats, one wavefront
}

extern "C" void kernel_launch(void* const* d_in, const int* in_sizes, int n_in,
                              void* d_out, int out_size)
{
    const float* h   = (const float*)d_in[0];   // [N_NODES, 128]
    const float* W   = (const float*)d_in[1];   // [10, 128]
    const int*   src = (const int*)d_in[2];     // [10, 100000] int32
    const int*   dst = (const int*)d_in[3];     // [10, 100000] int32
    const int*   rel = (const int*)d_in[4];     // [10] int32
    float* out = (float*)d_out;                 // [10, 100000]

    const int threads = 128;                     // 4 warps/block, 64 edges/block
    const int warps_needed = TOTAL_EDGES / EPW;  // 62500
    const int blocks = (warps_needed * 32 + threads - 1) / threads;  // 15625
    distmult_kernel<<<blocks, threads>>>(h, W, src, dst, rel, out);
}